// round 11
// baseline (speedup 1.0000x reference)
#include <cuda_runtime.h>
#include <cstdint>

// Problem constants
#define LDX     1025          // x row length (1024 feats + 1 condition)
#define NDIM    1024
#define NBASIS  6

// Tiling
#define BM 128
#define NKC 192               // 32 d-chunks * 6 basis

#define PSTRIDE 20            // float2 per row (16 used + 4 pad -> conflict-free frag loads)
#define A_BYTES (128 * PSTRIDE * 8)          // 20480 per A stage
#define B_BYTES (128 * PSTRIDE * 8)          // 20480 per B stage
#define SMEM_DYN (2 * A_BYTES + 3 * B_BYTES) // 102400: 2-stage A + 3-stage B ring

#define NTHREADS 512

__device__ __forceinline__ uint32_t f2tf32(float f) {
    uint32_t u; asm("cvt.rna.tf32.f32 %0, %1;" : "=r"(u) : "f"(f)); return u;
}

__device__ __forceinline__ void mma_tf32(float* d, const uint32_t* a,
                                         uint32_t b0, uint32_t b1) {
    asm volatile(
        "mma.sync.aligned.m16n8k8.row.col.f32.tf32.tf32.f32 "
        "{%0,%1,%2,%3}, {%4,%5,%6,%7}, {%8,%9}, {%0,%1,%2,%3};"
        : "+f"(d[0]), "+f"(d[1]), "+f"(d[2]), "+f"(d[3])
        : "r"(a[0]), "r"(a[1]), "r"(a[2]), "r"(a[3]), "r"(b0), "r"(b1));
}

__global__ void __launch_bounds__(NTHREADS, 1)
vclinear_mma(const float* __restrict__ x, const float* __restrict__ w,
             const float* __restrict__ bias, float* __restrict__ out)
{
    extern __shared__ char dsm[];
    float2* ast[2];
    ast[0] = reinterpret_cast<float2*>(dsm);                     // A ping
    ast[1] = reinterpret_cast<float2*>(dsm + A_BYTES);           // A pong
    float2* bst[3];
    bst[0] = reinterpret_cast<float2*>(dsm + 2 * A_BYTES);
    bst[1] = reinterpret_cast<float2*>(dsm + 2 * A_BYTES + B_BYTES);
    bst[2] = reinterpret_cast<float2*>(dsm + 2 * A_BYTES + 2 * B_BYTES);

    __shared__ float basis_s[BM * NBASIS];

    const int t    = threadIdx.x;
    const int wid  = t >> 5;
    const int lane = t & 31;
    const int g    = lane >> 2;          // group id (0..7)
    const int q4   = lane & 3;           // thread-in-group (0..3)
    const int wm   = (wid >> 2) * 32;    // 4 warps in M
    const int wn   = (wid & 3) * 32;     // 4 warps in N
    const int m0   = (blockIdx.x & 255) << 7;   // 256 M-tiles
    const int n0   = (blockIdx.x >> 8) << 7;    // 8 N-tiles; consecutive CTAs share n0

    // fill-role indices (512 threads: each loads 8 values per tile)
    const int eB   = t & 127;            // row/col within tile
    const int qtr  = t >> 7;             // which 8 of the 32 k-values (0..3)

    // basis per CTA row
    if (t < BM) {
        float tc = x[(size_t)(m0 + t) * LDX + NDIM];
        float* bs = &basis_s[t * NBASIS];
        bs[0] = 1.0f; bs[1] = tc; bs[2] = tc * tc;
        float r1 = fmaxf(tc - 0.25f, 0.0f);
        float r2 = fmaxf(tc - 0.50f, 0.0f);
        float r3 = fmaxf(tc - 0.75f, 0.0f);
        bs[3] = r1 * r1; bs[4] = r2 * r2; bs[5] = r3 * r3;
    }

    float acc[2][4][4];
    #pragma unroll
    for (int i = 0; i < 2; ++i)
        #pragma unroll
        for (int j = 0; j < 4; ++j)
            #pragma unroll
            for (int v = 0; v < 4; ++v) acc[i][j][v] = 0.0f;

    float vB[8], vA[8];

    // ---- fill helpers ----
    auto fillB = [&](int kc) {
        const int c  = kc % NBASIS;
        const int d0 = (kc / NBASIS) << 5;
        const float* wb = w + ((size_t)c << 20) + ((size_t)(d0 + (qtr << 3)) << 10) + n0 + eB;
        #pragma unroll
        for (int m = 0; m < 8; ++m) vB[m] = wb[(size_t)m << 10];
    };
    auto storeB = [&](float2* dst) {
        #pragma unroll
        for (int q = 0; q < 4; ++q) {
            float2 v;
            v.x = __uint_as_float(f2tf32(vB[q]));
            v.y = __uint_as_float(f2tf32(vB[q + 4]));
            dst[eB * PSTRIDE + (qtr << 2) + q] = v;     // slot s=qtr, pair q
        }
    };
    auto fillA = [&](int kc) {
        const int d0 = (kc / NBASIS) << 5;
        const float* xa = x + (size_t)(m0 + eB) * LDX + d0 + (qtr << 3);
        #pragma unroll
        for (int m = 0; m < 8; ++m) vA[m] = xa[m];
    };
    auto storeA = [&](float2* dst) {
        #pragma unroll
        for (int q = 0; q < 4; ++q)
            dst[eB * PSTRIDE + (qtr << 2) + q] = make_float2(vA[q], vA[q + 4]);
    };

    // ---- prologue: stage chunks 0,1 and d-chunk-0 feats into A ping ----
    fillB(0); fillA(0);
    storeB(bst[0]); storeA(ast[0]);
    fillB(1);
    __syncthreads();            // basis_s + bst[0] + ast[0] visible
    storeB(bst[1]);             // read at chunk 1 (one barrier later)

    // ---- mainloop: ONE barrier per chunk, 3-stage B ring, 2-stage A ping-pong ----
    for (int kc = 0; kc < NKC; ++kc) {
        const int c  = kc % NBASIS;
        const int dc = kc / NBASIS;

        // per-chunk basis scalars
        float bs1[2], bs2[2];
        #pragma unroll
        for (int i = 0; i < 2; ++i) {
            bs1[i] = basis_s[(wm + i * 16 + g) * NBASIS + c];
            bs2[i] = basis_s[(wm + i * 16 + 8 + g) * NBASIS + c];
        }

        // prefetch LDGs fly under the MMAs
        const bool pfB = (kc + 2) < NKC;
        if (pfB) fillB(kc + 2);
        if (c == 3 && (kc + 3) < NKC) fillA(kc + 3);    // next d-chunk's feats

        float2* const bcur = bst[kc % 3];
        float2* const acur = ast[dc & 1];

        #pragma unroll
        for (int s = 0; s < 4; ++s) {
            uint32_t a[2][4];
            #pragma unroll
            for (int i = 0; i < 2; ++i) {
                float2 p0 = acur[(wm + i * 16 + g) * PSTRIDE + s * 4 + q4];
                float2 p1 = acur[(wm + i * 16 + 8 + g) * PSTRIDE + s * 4 + q4];
                a[i][0] = f2tf32(p0.x * bs1[i]);
                a[i][2] = f2tf32(p0.y * bs1[i]);
                a[i][1] = f2tf32(p1.x * bs2[i]);
                a[i][3] = f2tf32(p1.y * bs2[i]);
            }
            #pragma unroll
            for (int j = 0; j < 4; ++j) {
                float2 pb = bcur[(wn + j * 8 + g) * PSTRIDE + s * 4 + q4];
                uint32_t b0 = __float_as_uint(pb.x);
                uint32_t b1 = __float_as_uint(pb.y);
                mma_tf32(acc[0][j], a[0], b0, b1);
                mma_tf32(acc[1][j], a[1], b0, b1);
            }
        }

        // store-ahead-2: buffer (kc+2)%3 was last read at chunk kc-1 (>=1 barrier ago)
        if (pfB) storeB(bst[(kc + 2) % 3]);
        // next d-chunk feats -> OTHER A buffer; its last reader finished 5 barriers ago
        if (c == 4 && (kc + 2) < NKC) storeA(ast[(dc + 1) & 1]);

        __syncthreads();
    }

    // ---- epilogue: direct STG.64 with bias ----
    #pragma unroll
    for (int j = 0; j < 4; ++j) {
        const int col = n0 + wn + j * 8 + q4 * 2;
        const float2 bb = *reinterpret_cast<const float2*>(bias + col);
        #pragma unroll
        for (int i = 0; i < 2; ++i) {
            const int r1 = m0 + wm + i * 16 + g;
            float2 v1 = make_float2(acc[i][j][0] + bb.x, acc[i][j][1] + bb.y);
            float2 v2 = make_float2(acc[i][j][2] + bb.x, acc[i][j][3] + bb.y);
            *reinterpret_cast<float2*>(out + (size_t)r1 * NDIM + col) = v1;
            *reinterpret_cast<float2*>(out + (size_t)(r1 + 8) * NDIM + col) = v2;
        }
    }
}

// ---------------- launch ----------------
extern "C" void kernel_launch(void* const* d_in, const int* in_sizes, int n_in,
                              void* d_out, int out_size) {
    (void)in_sizes; (void)n_in; (void)out_size;
    const float* x    = (const float*)d_in[0];
    const float* w    = (const float*)d_in[1];
    const float* bias = (const float*)d_in[2];
    float* out = (float*)d_out;

    cudaFuncSetAttribute(vclinear_mma, cudaFuncAttributeMaxDynamicSharedMemorySize, SMEM_DYN);
    // 256 consecutive CTAs share an N-tile -> weight slice stays L2-hot
    vclinear_mma<<<2048, NTHREADS, SMEM_DYN>>>(x, w, bias, out);
}

// round 12
// speedup vs baseline: 1.1405x; 1.1405x over previous
#include <cuda_runtime.h>
#include <cstdint>

// Problem constants
#define LDX     1025          // x row length (1024 feats + 1 condition)
#define NDIM    1024
#define NBASIS  6

// Tiling
#define BM 128
#define NKC 192               // 32 d-chunks * 6 basis

#define PSTRIDE 20            // float2 per row (16 used + 4 pad -> conflict-free frag loads)
#define A_BYTES (128 * PSTRIDE * 8)          // 20480
#define B_BYTES (128 * PSTRIDE * 8)          // 20480 per stage
#define SMEM_DYN (A_BYTES + 3 * B_BYTES)     // 81920: A + 3-stage B ring

__device__ __forceinline__ uint32_t f2tf32(float f) {
    uint32_t u; asm("cvt.rna.tf32.f32 %0, %1;" : "=r"(u) : "f"(f)); return u;
}

__device__ __forceinline__ void mma_tf32(float* d, const uint32_t* a,
                                         uint32_t b0, uint32_t b1) {
    asm volatile(
        "mma.sync.aligned.m16n8k8.row.col.f32.tf32.tf32.f32 "
        "{%0,%1,%2,%3}, {%4,%5,%6,%7}, {%8,%9}, {%0,%1,%2,%3};"
        : "+f"(d[0]), "+f"(d[1]), "+f"(d[2]), "+f"(d[3])
        : "r"(a[0]), "r"(a[1]), "r"(a[2]), "r"(a[3]), "r"(b0), "r"(b1));
}

__global__ void __launch_bounds__(256, 1)
vclinear_mma(const float* __restrict__ x, const float* __restrict__ w,
             const float* __restrict__ bias, float* __restrict__ out)
{
    extern __shared__ char dsm[];
    float2* const apf = reinterpret_cast<float2*>(dsm);              // A: raw fp32 pairs
    float2* bst[3];
    bst[0] = reinterpret_cast<float2*>(dsm + A_BYTES);
    bst[1] = reinterpret_cast<float2*>(dsm + A_BYTES + B_BYTES);
    bst[2] = reinterpret_cast<float2*>(dsm + A_BYTES + 2 * B_BYTES);

    __shared__ float basis_s[BM * NBASIS];

    const int t    = threadIdx.x;
    const int wid  = t >> 5;
    const int lane = t & 31;
    const int g    = lane >> 2;          // group id (0..7)
    const int q4   = lane & 3;           // thread-in-group (0..3)
    const int wm   = (wid >> 1) * 32;    // 4 warps in M
    const int wn   = (wid & 1) * 64;     // 2 warps in N
    const int m0   = (blockIdx.x & 255) << 7;   // 256 M-tiles
    const int n0   = (blockIdx.x >> 8) << 7;    // 8 N-tiles; consecutive CTAs share n0

    // fill-role indices (256 threads: each loads 16 values per tile)
    const int eB   = t & 127;            // row/col within tile
    const int half = t >> 7;             // which 16 of the 32 k-values

    // basis per CTA row
    if (t < BM) {
        float tc = x[(size_t)(m0 + t) * LDX + NDIM];
        float* bs = &basis_s[t * NBASIS];
        bs[0] = 1.0f; bs[1] = tc; bs[2] = tc * tc;
        float r1 = fmaxf(tc - 0.25f, 0.0f);
        float r2 = fmaxf(tc - 0.50f, 0.0f);
        float r3 = fmaxf(tc - 0.75f, 0.0f);
        bs[3] = r1 * r1; bs[4] = r2 * r2; bs[5] = r3 * r3;
    }

    float acc[2][8][4];
    #pragma unroll
    for (int i = 0; i < 2; ++i)
        #pragma unroll
        for (int j = 0; j < 8; ++j)
            #pragma unroll
            for (int v = 0; v < 4; ++v) acc[i][j][v] = 0.0f;

    // persistent raw A fragments for the current d-chunk
    float2 araw[2][4][2];

    float vB0[16], vB1[16], vA[16];      // in-flight LDG holding registers

    // ---- fill helpers ----
    auto fillB = [&](int kc, float* v) {
        const int c  = kc % NBASIS;
        const int d0 = (kc / NBASIS) << 5;
        const float* wb = w + ((size_t)c << 20) + ((size_t)(d0 + (half << 4)) << 10) + n0 + eB;
        #pragma unroll
        for (int m = 0; m < 16; ++m) v[m] = wb[(size_t)m << 10];
    };
    auto storeB = [&](const float* v, float2* dst) {
        #pragma unroll
        for (int s2 = 0; s2 < 2; ++s2)
            #pragma unroll
            for (int q = 0; q < 4; ++q) {
                int sq = ((half << 1) + s2) * 4 + q;
                float2 pv;
                pv.x = __uint_as_float(f2tf32(v[s2 * 8 + q]));
                pv.y = __uint_as_float(f2tf32(v[s2 * 8 + q + 4]));
                dst[eB * PSTRIDE + sq] = pv;
            }
    };
    auto fillA = [&](int kc) {
        const int d0 = (kc / NBASIS) << 5;
        const float* xa = x + (size_t)(m0 + eB) * LDX + d0 + (half << 4);
        #pragma unroll
        for (int m = 0; m < 16; ++m) vA[m] = xa[m];
    };
    auto storeA = [&]() {
        #pragma unroll
        for (int s2 = 0; s2 < 2; ++s2)
            #pragma unroll
            for (int q = 0; q < 4; ++q) {
                int sq = ((half << 1) + s2) * 4 + q;
                apf[eB * PSTRIDE + sq] = make_float2(vA[s2 * 8 + q], vA[s2 * 8 + q + 4]);
            }
    };

    // ---- chunk body: deep-prefetch schedule ----
    // at chunk kc: fillB(kc+3) -> fillv (held 2 chunk bodies)
    //              storeB(storev -> bst[(kc+2)%3])  (filled at chunk kc-1)
    auto chunk = [&](int kc, int c, float* fillv, const float* storev,
                     int rcur, int rtgt) {
        if (c == 0) {            // new d-chunk: reload persistent A fragments
            #pragma unroll
            for (int i = 0; i < 2; ++i)
                #pragma unroll
                for (int s = 0; s < 4; ++s) {
                    araw[i][s][0] = apf[(wm + i * 16 + g) * PSTRIDE + s * 4 + q4];
                    araw[i][s][1] = apf[(wm + i * 16 + 8 + g) * PSTRIDE + s * 4 + q4];
                }
        }
        float bs1[2], bs2[2];
        #pragma unroll
        for (int i = 0; i < 2; ++i) {
            bs1[i] = basis_s[(wm + i * 16 + g) * NBASIS + c];
            bs2[i] = basis_s[(wm + i * 16 + 8 + g) * NBASIS + c];
        }

        if (kc + 3 < NKC) fillB(kc + 3, fillv);       // LDGs fly for ~2 chunks
        if (c == 2 && kc + 4 < NKC) fillA(kc + 4);    // next d-chunk feats

        float2* const bcur = bst[rcur];
        const int bbase = (wn + g) * PSTRIDE + q4;

        // software-pipelined fragment units: u = (s, jhalf)
        float2 bf0[4], bf1[4];
        uint32_t a[2][4];
        #pragma unroll
        for (int j = 0; j < 4; ++j) bf0[j] = bcur[bbase + j * 8 * PSTRIDE];

        #pragma unroll
        for (int u = 0; u < 8; ++u) {
            const int s  = u >> 1;
            const int jh = u & 1;
            float2* cur = (u & 1) ? bf1 : bf0;
            float2* nxt = (u & 1) ? bf0 : bf1;
            if (u < 7) {                               // prefetch next unit's frags
                const int un = u + 1, sn = un >> 1, jn = un & 1;
                #pragma unroll
                for (int j = 0; j < 4; ++j)
                    nxt[j] = bcur[bbase + (jn * 4 + j) * 8 * PSTRIDE + sn * 4];
            }
            if (jh == 0) {                             // new k-slice: refresh A frags
                #pragma unroll
                for (int i = 0; i < 2; ++i) {
                    a[i][0] = f2tf32(araw[i][s][0].x * bs1[i]);
                    a[i][2] = f2tf32(araw[i][s][0].y * bs1[i]);
                    a[i][1] = f2tf32(araw[i][s][1].x * bs2[i]);
                    a[i][3] = f2tf32(araw[i][s][1].y * bs2[i]);
                }
            }
            #pragma unroll
            for (int j = 0; j < 4; ++j) {
                const int jj = jh * 4 + j;
                uint32_t b0 = __float_as_uint(cur[j].x);
                uint32_t b1 = __float_as_uint(cur[j].y);
                mma_tf32(acc[0][jj], a[0], b0, b1);
                mma_tf32(acc[1][jj], a[1], b0, b1);
            }
        }

        if (kc + 2 < NKC) storeB(storev, bst[rtgt]);   // data fetched at chunk kc-1
        if (c == 4 && kc + 2 < NKC) storeA();
        __syncthreads();
    };

    // ---- prologue: chunks 0,1 staged directly; chunk-2 data held in vB0 ----
    fillB(0, vB0); fillA(0);
    storeB(vB0, bst[0]); storeA();
    fillB(1, vB0); storeB(vB0, bst[1]);
    fillB(2, vB0);                        // stored at end of chunk 0
    __syncthreads();

    // ---- mainloop: pairs (c,c+1) of same d-chunk; static vB parity ----
    int rA = 0, c0 = 0;
    for (int kp = 0; kp < NKC; kp += 2) {
        const int rB = (rA + 1 == 3) ? 0 : rA + 1;
        const int tA = (rA + 2 >= 3) ? rA - 1 : rA + 2;
        const int tB = (rB + 2 >= 3) ? rB - 1 : rB + 2;
        // kc even: fill target (kc+3)&1=1 -> vB1, store source (kc+2)&1=0 -> vB0
        chunk(kp,     c0,     vB1, vB0, rA, tA);
        // kc odd : fill -> vB0, store -> vB1
        chunk(kp + 1, c0 + 1, vB0, vB1, rB, tB);
        rA = tB == 0 ? (rA + 2) % 3 : (rA + 2) % 3;   // advance ring by 2
        c0 += 2; if (c0 == NBASIS) c0 = 0;
    }

    // ---- epilogue: direct STG.64 with bias ----
    #pragma unroll
    for (int j = 0; j < 8; ++j) {
        const int col = n0 + wn + j * 8 + q4 * 2;
        const float2 bb = *reinterpret_cast<const float2*>(bias + col);
        #pragma unroll
        for (int i = 0; i < 2; ++i) {
            const int r1 = m0 + wm + i * 16 + g;
            float2 v1 = make_float2(acc[i][j][0] + bb.x, acc[i][j][1] + bb.y);
            float2 v2 = make_float2(acc[i][j][2] + bb.x, acc[i][j][3] + bb.y);
            *reinterpret_cast<float2*>(out + (size_t)r1 * NDIM + col) = v1;
            *reinterpret_cast<float2*>(out + (size_t)(r1 + 8) * NDIM + col) = v2;
        }
    }
}

// ---------------- launch ----------------
extern "C" void kernel_launch(void* const* d_in, const int* in_sizes, int n_in,
                              void* d_out, int out_size) {
    (void)in_sizes; (void)n_in; (void)out_size;
    const float* x    = (const float*)d_in[0];
    const float* w    = (const float*)d_in[1];
    const float* bias = (const float*)d_in[2];
    float* out = (float*)d_out;

    cudaFuncSetAttribute(vclinear_mma, cudaFuncAttributeMaxDynamicSharedMemorySize, SMEM_DYN);
    // 256 consecutive CTAs share an N-tile -> weight slice stays L2-hot
    vclinear_mma<<<2048, 256, SMEM_DYN>>>(x, w, bias, out);
}

// round 17
// speedup vs baseline: 1.8100x; 1.5870x over previous
#include <cuda_runtime.h>
#include <cstdint>

// Problem constants
#define LDX     1025          // x row length (1024 feats + 1 condition)
#define NDIM    1024
#define NBASIS  6

// Tiling
#define BM 128
#define NKC 192               // 32 d-chunks * 6 basis

// Shared layouts (floats)
#define A_ROW   36            // 32 k + 4 pad  -> frag bank = (4*row + k) % 32, conflict-free
#define A_FLOATS (128 * A_ROW)            // 4608 floats = 18432 B per stage
#define B_ROW   132           // 128 e + 4 pad -> frag bank = (4*k + e) % 32, conflict-free
#define B_FLOATS (32 * B_ROW)             // 4224 floats = 16896 B per stage
#define SMEM_DYN ((2 * A_FLOATS + 3 * B_FLOATS) * 4)   // 87552 B

__device__ __forceinline__ uint32_t f2tf32(float f) {
    uint32_t u; asm("cvt.rna.tf32.f32 %0, %1;" : "=r"(u) : "f"(f)); return u;
}

__device__ __forceinline__ void mma_tf32(float* d, const uint32_t* a,
                                         uint32_t b0, uint32_t b1) {
    asm volatile(
        "mma.sync.aligned.m16n8k8.row.col.f32.tf32.tf32.f32 "
        "{%0,%1,%2,%3}, {%4,%5,%6,%7}, {%8,%9}, {%0,%1,%2,%3};"
        : "+f"(d[0]), "+f"(d[1]), "+f"(d[2]), "+f"(d[3])
        : "r"(a[0]), "r"(a[1]), "r"(a[2]), "r"(a[3]), "r"(b0), "r"(b1));
}

#define CP_COMMIT() asm volatile("cp.async.commit_group;" ::: "memory")
#define CP_WAIT1()  asm volatile("cp.async.wait_group 1;" ::: "memory")
#define CP_WAIT0()  asm volatile("cp.async.wait_group 0;" ::: "memory")

__global__ void __launch_bounds__(256, 2)
vclinear_mma(const float* __restrict__ x, const float* __restrict__ w,
             const float* __restrict__ bias, float* __restrict__ out)
{
    extern __shared__ float dsm[];
    float* const ast0 = dsm;                         // A ping
    float* const ast1 = dsm + A_FLOATS;              // A pong
    float* const bbase = dsm + 2 * A_FLOATS;         // B ring (3 stages)

    __shared__ float basis_s[BM * NBASIS];

    const int t    = threadIdx.x;
    const int wid  = t >> 5;
    const int lane = t & 31;
    const int g    = lane >> 2;          // group id (0..7)
    const int q4   = lane & 3;           // thread-in-group (0..3)
    const int wm   = (wid >> 1) * 32;    // 4 warps in M
    const int wn   = (wid & 1) * 64;     // 2 warps in N
    const int m0   = (blockIdx.x & 255) << 7;   // 256 M-tiles
    const int n0   = (blockIdx.x >> 8) << 7;    // 8 N-tiles; consecutive CTAs share n0

    // fill-role indices
    const int eB   = t & 127;            // A fill: row within tile
    const int half = t >> 7;             // A fill: which 16 k
    const int bk   = t >> 3;             // B fill: k row (0..31)
    const int bseg = t & 7;              // B fill: 16B segment base

    // ---- B fill: cp.async, 4x16B per thread ----
    const uint32_t bsm_dyn = (uint32_t)__cvta_generic_to_shared(bbase);
    auto fillB_async = [&](int kc) {
        const int c  = kc % NBASIS;
        const int d0 = (kc / NBASIS) << 5;
        const int st = kc % 3;
        const float* src = w + ((size_t)c << 20) + ((size_t)(d0 + bk) << 10)
                             + n0 + (bseg << 2);
        uint32_t dst = bsm_dyn + (uint32_t)st * (B_FLOATS * 4)
                     + (uint32_t)bk * (B_ROW * 4) + ((uint32_t)bseg << 4);
        #pragma unroll
        for (int u = 0; u < 4; ++u)
            asm volatile("cp.async.cg.shared.global [%0], [%1], 16;"
                         :: "r"(dst + (u << 7)), "l"(src + (u << 5)) : "memory");
    };

    // ---- A fill (plain LDG -> regs -> STS, every 6 chunks) ----
    float vA[16];
    auto fillA = [&](int kc) {
        const int d0 = (kc / NBASIS) << 5;
        const float* xa = x + (size_t)(m0 + eB) * LDX + d0 + (half << 4);
        #pragma unroll
        for (int m = 0; m < 16; ++m) vA[m] = xa[m];
    };
    auto storeA = [&](float* dst) {
        float* p = dst + eB * A_ROW + (half << 4);
        #pragma unroll
        for (int m = 0; m < 4; ++m)
            reinterpret_cast<float4*>(p)[m] =
                make_float4(vA[m * 4], vA[m * 4 + 1], vA[m * 4 + 2], vA[m * 4 + 3]);
    };

    // basis per CTA row
    if (t < BM) {
        float tc = x[(size_t)(m0 + t) * LDX + NDIM];
        float* bs = &basis_s[t * NBASIS];
        bs[0] = 1.0f; bs[1] = tc; bs[2] = tc * tc;
        float r1 = fmaxf(tc - 0.25f, 0.0f);
        float r2 = fmaxf(tc - 0.50f, 0.0f);
        float r3 = fmaxf(tc - 0.75f, 0.0f);
        bs[3] = r1 * r1; bs[4] = r2 * r2; bs[5] = r3 * r3;
    }

    float acc[2][8][4];
    #pragma unroll
    for (int i = 0; i < 2; ++i)
        #pragma unroll
        for (int j = 0; j < 8; ++j)
            #pragma unroll
            for (int v = 0; v < 4; ++v) acc[i][j][v] = 0.0f;

    // ---- prologue ----
    fillB_async(0); CP_COMMIT();
    fillB_async(1); CP_COMMIT();
    fillA(0); storeA(ast0);
    // (top-of-chunk-0 barrier publishes basis_s, ast0, and waits B0)

    // ---- mainloop: ONE barrier per chunk, cp.async 3-stage B ring, A ping-pong ----
    for (int kc = 0; kc < NKC; ++kc) {
        const int c  = kc % NBASIS;
        const int dc = kc / NBASIS;

        if (kc + 1 < NKC) { CP_WAIT1(); } else { CP_WAIT0(); }
        __syncthreads();                      // stage kc%3 + A buffer visible to all

        if (kc + 2 < NKC) { fillB_async(kc + 2); CP_COMMIT(); }
        if (c == 3 && kc + 3 < NKC) fillA(kc + 3);

        const float* As = (dc & 1) ? ast1 : ast0;
        const float* Bs = bbase + (kc % 3) * B_FLOATS;

        float bs1[2], bs2[2];
        #pragma unroll
        for (int i = 0; i < 2; ++i) {
            bs1[i] = basis_s[(wm + i * 16 + g) * NBASIS + c];
            bs2[i] = basis_s[(wm + i * 16 + 8 + g) * NBASIS + c];
        }

        #pragma unroll
        for (int s = 0; s < 4; ++s) {
            const int k0 = s * 8 + q4;        // FIX: MMA slice s covers logical k [8s, 8s+8)
            uint32_t a[2][4];
            #pragma unroll
            for (int i = 0; i < 2; ++i) {
                const int r0 = wm + i * 16 + g;
                float f0 = As[r0 * A_ROW + k0];
                float f1 = As[(r0 + 8) * A_ROW + k0];
                float f2 = As[r0 * A_ROW + k0 + 4];
                float f3 = As[(r0 + 8) * A_ROW + k0 + 4];
                a[i][0] = f2tf32(f0 * bs1[i]);
                a[i][1] = f2tf32(f1 * bs2[i]);
                a[i][2] = f2tf32(f2 * bs1[i]);
                a[i][3] = f2tf32(f3 * bs2[i]);
            }
            #pragma unroll
            for (int j = 0; j < 8; ++j) {
                const int e = wn + j * 8 + g;
                uint32_t b0 = f2tf32(Bs[k0 * B_ROW + e]);
                uint32_t b1 = f2tf32(Bs[(k0 + 4) * B_ROW + e]);
                mma_tf32(acc[0][j], a[0], b0, b1);
                mma_tf32(acc[1][j], a[1], b0, b1);
            }
        }

        // next d-chunk feats -> other A buffer (last read 5 barriers ago)
        if (c == 4 && kc + 2 < NKC) storeA((dc & 1) ? ast0 : ast1);
    }

    // ---- epilogue: direct STG.64 with bias ----
    #pragma unroll
    for (int j = 0; j < 8; ++j) {
        const int col = n0 + wn + j * 8 + q4 * 2;
        const float2 bb = *reinterpret_cast<const float2*>(bias + col);
        #pragma unroll
        for (int i = 0; i < 2; ++i) {
            const int r1 = m0 + wm + i * 16 + g;
            float2 v1 = make_float2(acc[i][j][0] + bb.x, acc[i][j][1] + bb.y);
            float2 v2 = make_float2(acc[i][j][2] + bb.x, acc[i][j][3] + bb.y);
            *reinterpret_cast<float2*>(out + (size_t)r1 * NDIM + col) = v1;
            *reinterpret_cast<float2*>(out + (size_t)(r1 + 8) * NDIM + col) = v2;
        }
    }
}

// ---------------- launch ----------------
extern "C" void kernel_launch(void* const* d_in, const int* in_sizes, int n_in,
                              void* d_out, int out_size) {
    (void)in_sizes; (void)n_in; (void)out_size;
    const float* x    = (const float*)d_in[0];
    const float* w    = (const float*)d_in[1];
    const float* bias = (const float*)d_in[2];
    float* out = (float*)d_out;

    cudaFuncSetAttribute(vclinear_mma, cudaFuncAttributeMaxDynamicSharedMemorySize, SMEM_DYN);
    // 256 consecutive CTAs share an N-tile -> weight slice stays L2-hot
    vclinear_mma<<<2048, 256, SMEM_DYN>>>(x, w, bias, out);
}